// round 8
// baseline (speedup 1.0000x reference)
#include <cuda_runtime.h>
#include <math.h>

#define SLEN 2048
#define BSZ 4
#define DM 1024
#define NH 16
#define DH 64
#define NQKVB 3088          // NH*(3*DH+1)
#define M_ROWS 8192         // SLEN*BSZ
#define EPSF 1e-5f
#define SCALEF 0.125f       // 1/sqrt(64)

// ---------------- scratch (static device globals; no allocation) ----------------
// g_qkvb doubles as the output-projection result buffer (qkvb dead after split).
__device__ float g_qkvb[M_ROWS * NQKVB];     // [m][3088]; later: attn [m][1024]
__device__ float g_q[64 * SLEN * DH];        // [b*16+h][l][d]
__device__ float g_k[64 * SLEN * DH];
__device__ float g_v[64 * SLEN * DH];
__device__ float g_beta[64 * SLEN];
__device__ float g_lo[M_ROWS * DM];          // layer_out in [l][b][h*d] layout

// ---------------- fp32 GEMM: C[m][n] = sum_k A[m][k] * B[n][k] ----------------
// BM=BN=128, BK=16, 256 threads, 8x8 microtile, warp-tiled 4x2 layout,
// register-prefetch double buffering. M % 128 == 0, K % 16 == 0, N % 4 == 0.
__device__ __forceinline__ void gemm_abt_128x128(const float* __restrict__ A,
                                                 const float* __restrict__ B,
                                                 float* __restrict__ C,
                                                 int N, int K) {
    __shared__ float As[16][132];
    __shared__ float Bs[16][132];
    const int tid = threadIdx.x;
    const int bm = blockIdx.y * 128;
    const int bn = blockIdx.x * 128;

    // loaders
    const int lr = tid >> 2;          // 0..63
    const int lk = (tid & 3) << 2;    // 0,4,8,12

    // warp-tiled compute mapping: 8 warps in 4x2; each warp 32 rows x 64 cols;
    // lane: lr2 = lane>>3 (row group of 8), lc2 = lane&7 (col group of 8)
    const int w = tid >> 5;
    const int lane = tid & 31;
    const int trow = (w >> 1) * 32 + (lane >> 3) * 8;
    const int tcol = (w & 1) * 64 + (lane & 7) * 8;

    const float* pa0 = A + (size_t)(bm + lr) * K + lk;
    const float* pa1 = A + (size_t)(bm + lr + 64) * K + lk;
    const int nb0 = bn + lr, nb1 = bn + lr + 64;
    const float* pb0 = B + (size_t)(nb0 < N ? nb0 : 0) * K + lk;
    const float* pb1 = B + (size_t)(nb1 < N ? nb1 : 0) * K + lk;
    const bool v0 = (nb0 < N), v1 = (nb1 < N);

    float acc[8][8];
#pragma unroll
    for (int i = 0; i < 8; i++)
#pragma unroll
        for (int j = 0; j < 8; j++) acc[i][j] = 0.f;

    float4 a0 = *(const float4*)(pa0);
    float4 a1 = *(const float4*)(pa1);
    float4 b0 = make_float4(0.f, 0.f, 0.f, 0.f);
    float4 b1 = make_float4(0.f, 0.f, 0.f, 0.f);
    if (v0) b0 = *(const float4*)(pb0);
    if (v1) b1 = *(const float4*)(pb1);

    for (int k0 = 0; k0 < K; k0 += 16) {
        As[lk + 0][lr] = a0.x; As[lk + 1][lr] = a0.y;
        As[lk + 2][lr] = a0.z; As[lk + 3][lr] = a0.w;
        As[lk + 0][lr + 64] = a1.x; As[lk + 1][lr + 64] = a1.y;
        As[lk + 2][lr + 64] = a1.z; As[lk + 3][lr + 64] = a1.w;
        Bs[lk + 0][lr] = b0.x; Bs[lk + 1][lr] = b0.y;
        Bs[lk + 2][lr] = b0.z; Bs[lk + 3][lr] = b0.w;
        Bs[lk + 0][lr + 64] = b1.x; Bs[lk + 1][lr + 64] = b1.y;
        Bs[lk + 2][lr + 64] = b1.z; Bs[lk + 3][lr + 64] = b1.w;
        __syncthreads();

        if (k0 + 16 < K) {   // prefetch next tile; overlaps FFMA block
            a0 = *(const float4*)(pa0 + k0 + 16);
            a1 = *(const float4*)(pa1 + k0 + 16);
            if (v0) b0 = *(const float4*)(pb0 + k0 + 16);
            if (v1) b1 = *(const float4*)(pb1 + k0 + 16);
        }

#pragma unroll
        for (int kk = 0; kk < 16; kk++) {
            float4 af0 = *(const float4*)&As[kk][trow];
            float4 af1 = *(const float4*)&As[kk][trow + 4];
            float4 bf0 = *(const float4*)&Bs[kk][tcol];
            float4 bf1 = *(const float4*)&Bs[kk][tcol + 4];
            float a[8] = {af0.x, af0.y, af0.z, af0.w, af1.x, af1.y, af1.z, af1.w};
            float b[8] = {bf0.x, bf0.y, bf0.z, bf0.w, bf1.x, bf1.y, bf1.z, bf1.w};
#pragma unroll
            for (int i = 0; i < 8; i++)
#pragma unroll
                for (int j = 0; j < 8; j++) acc[i][j] = fmaf(a[i], b[j], acc[i][j]);
        }
        __syncthreads();
    }

#pragma unroll
    for (int i = 0; i < 8; i++) {
        int r = bm + trow + i;
#pragma unroll
        for (int jj = 0; jj < 2; jj++) {
            int c = bn + tcol + jj * 4;
            if (c < N) {  // N % 4 == 0 so float4 is all-in or all-out
                *(float4*)&C[(size_t)r * N + c] =
                    make_float4(acc[i][jj * 4 + 0], acc[i][jj * 4 + 1],
                                acc[i][jj * 4 + 2], acc[i][jj * 4 + 3]);
            }
        }
    }
}

__global__ __launch_bounds__(256, 2) void k_gemm_qkvb(const float* __restrict__ A,
                                                      const float* __restrict__ B) {
    gemm_abt_128x128(A, B, g_qkvb, NQKVB, DM);
}

// output projection writes into g_qkvb (reused as [m][1024])
__global__ __launch_bounds__(256, 2) void k_gemm_out(const float* __restrict__ B) {
    gemm_abt_128x128(g_lo, B, g_qkvb, DM, DM);
}

// ---------------- split + activations: 1 warp per (token m, head) -------------
__global__ __launch_bounds__(256) void k_split() {
    int gw = (blockIdx.x * blockDim.x + threadIdx.x) >> 5;   // 0..131071
    int lane = threadIdx.x & 31;
    int m = gw >> 4;        // token row (l*4 + b)
    int hd = gw & 15;
    int l = m >> 2;
    int b = m & 3;
    const float* base = g_qkvb + (size_t)m * NQKVB + hd * 193;

    size_t oidx = ((size_t)(b * 16 + hd) * SLEN + l) * DH + lane;

    // q : elu+1 then sum-normalize over the 64 dims
    float x0 = base[lane], x1 = base[lane + 32];
    float e0 = x0 > 0.f ? x0 + 1.f : expf(x0);
    float e1 = x1 > 0.f ? x1 + 1.f : expf(x1);
    float s = e0 + e1;
#pragma unroll
    for (int o = 16; o > 0; o >>= 1) s += __shfl_xor_sync(0xffffffffu, s, o);
    float inv = 1.f / s;
    g_q[oidx] = e0 * inv;
    g_q[oidx + 32] = e1 * inv;

    // k
    x0 = base[64 + lane]; x1 = base[96 + lane];
    e0 = x0 > 0.f ? x0 + 1.f : expf(x0);
    e1 = x1 > 0.f ? x1 + 1.f : expf(x1);
    s = e0 + e1;
#pragma unroll
    for (int o = 16; o > 0; o >>= 1) s += __shfl_xor_sync(0xffffffffu, s, o);
    inv = 1.f / s;
    g_k[oidx] = e0 * inv;
    g_k[oidx + 32] = e1 * inv;

    // v
    g_v[oidx] = base[128 + lane];
    g_v[oidx + 32] = base[160 + lane];

    // beta (sigmoid)
    if (lane == 0) {
        float br = base[192];
        g_beta[(size_t)(b * 16 + hd) * SLEN + l] = 1.f / (1.f + expf(-br));
    }
}

// ---------------- delta-rule recurrence: 1 CTA per (b,h), 128 threads ---------
// Thread pair (2*row, 2*row+1) owns W row `row`; each thread holds a 32-col
// half of W and of the cumsum acc in registers. Pair partials combined with
// shfl_xor(1) (same warp). 4 warps -> all 4 SMSPs busy. 2 bars/step.
__global__ __launch_bounds__(128) void k_recur() {
    const int bh = blockIdx.x;       // 0..63 = b*16 + h
    const int tid = threadIdx.x;     // 0..127
    const int row = tid >> 1;        // 0..63
    const int half = tid & 1;
    const int b = bh >> 4;
    const int hd = bh & 15;

    __shared__ __align__(16) float k_sh[64];
    __shared__ __align__(16) float q_sh[64];
    __shared__ float v_sh[64];

    float W[32], acc[32];
#pragma unroll
    for (int j = 0; j < 32; j++) { W[j] = 0.f; acc[j] = 0.f; }

    const float* __restrict__ kp = g_k + (size_t)bh * SLEN * DH;
    const float* __restrict__ qp = g_q + (size_t)bh * SLEN * DH;
    const float* __restrict__ vp = g_v + (size_t)bh * SLEN * DH;
    const float* __restrict__ bp = g_beta + (size_t)bh * SLEN;

    // prefetch t = 0
    float kn = 0.f, qn = 0.f, vn = 0.f;
    if (tid < 64) { kn = kp[tid]; vn = vp[tid]; }
    else          { qn = qp[tid - 64]; }
    float bn_ = bp[0];

    for (int t = 0; t < SLEN; t++) {
        if (tid < 64) { k_sh[tid] = kn; v_sh[tid] = vn; }
        else          { q_sh[tid - 64] = qn; }
        const float bc = bn_;
        __syncthreads();

        // copy this step's k/q halves + v into registers
        float kh[32], qh[32];
        const float4* k4 = (const float4*)(k_sh + half * 32);
        const float4* q4 = (const float4*)(q_sh + half * 32);
#pragma unroll
        for (int j = 0; j < 8; j++) {
            float4 kv = k4[j];
            kh[4 * j + 0] = kv.x; kh[4 * j + 1] = kv.y;
            kh[4 * j + 2] = kv.z; kh[4 * j + 3] = kv.w;
            float4 qv = q4[j];
            qh[4 * j + 0] = qv.x; qh[4 * j + 1] = qv.y;
            qh[4 * j + 2] = qv.z; qh[4 * j + 3] = qv.w;
        }
        const float vi = v_sh[row];
        __syncthreads();   // shared now free for next-iteration writes

        // prefetch next step (overlaps the ~400-cycle compute below)
        if (t + 1 < SLEN) {
            const size_t o = (size_t)(t + 1) * DH;
            if (tid < 64) { kn = kp[o + tid]; vn = vp[o + tid]; }
            else          { qn = qp[o + tid - 64]; }
            bn_ = bp[t + 1];
        }

        // kd partial (<acc_pre, k>) and vo partial (<W, k>) — independent, ILP
        float kd0 = 0.f, kd1 = 0.f, kd2 = 0.f, kd3 = 0.f;
        float vo0 = 0.f, vo1 = 0.f, vo2 = 0.f, vo3 = 0.f;
#pragma unroll
        for (int j = 0; j < 8; j++) {
            kd0 = fmaf(acc[4 * j + 0], kh[4 * j + 0], kd0);
            kd1 = fmaf(acc[4 * j + 1], kh[4 * j + 1], kd1);
            kd2 = fmaf(acc[4 * j + 2], kh[4 * j + 2], kd2);
            kd3 = fmaf(acc[4 * j + 3], kh[4 * j + 3], kd3);
            vo0 = fmaf(W[4 * j + 0], kh[4 * j + 0], vo0);
            vo1 = fmaf(W[4 * j + 1], kh[4 * j + 1], vo1);
            vo2 = fmaf(W[4 * j + 2], kh[4 * j + 2], vo2);
            vo3 = fmaf(W[4 * j + 3], kh[4 * j + 3], vo3);
        }
        float kdp = (kd0 + kd1) + (kd2 + kd3);
        float vop = (vo0 + vo1) + (vo2 + vo3);
        float kd = kdp + __shfl_xor_sync(0xffffffffu, kdp, 1);
        float vox = vop + __shfl_xor_sync(0xffffffffu, vop, 1);
        if (t == 0) kd = 1.f;
        const float s = 1.f / (kd + EPSF);
        const float ds = bc * kd * (vi - vox * s) * s;

        // W += ds*k; out = <W_new, q>; acc += k; den partial = <acc_post, q>
        float o0 = 0.f, o1 = 0.f, o2 = 0.f, o3 = 0.f;
        float d0 = 0.f, d1 = 0.f, d2 = 0.f, d3 = 0.f;
#pragma unroll
        for (int j = 0; j < 8; j++) {
            W[4 * j + 0] = fmaf(ds, kh[4 * j + 0], W[4 * j + 0]);
            o0 = fmaf(W[4 * j + 0], qh[4 * j + 0], o0);
            acc[4 * j + 0] += kh[4 * j + 0];
            d0 = fmaf(acc[4 * j + 0], qh[4 * j + 0], d0);

            W[4 * j + 1] = fmaf(ds, kh[4 * j + 1], W[4 * j + 1]);
            o1 = fmaf(W[4 * j + 1], qh[4 * j + 1], o1);
            acc[4 * j + 1] += kh[4 * j + 1];
            d1 = fmaf(acc[4 * j + 1], qh[4 * j + 1], d1);

            W[4 * j + 2] = fmaf(ds, kh[4 * j + 2], W[4 * j + 2]);
            o2 = fmaf(W[4 * j + 2], qh[4 * j + 2], o2);
            acc[4 * j + 2] += kh[4 * j + 2];
            d2 = fmaf(acc[4 * j + 2], qh[4 * j + 2], d2);

            W[4 * j + 3] = fmaf(ds, kh[4 * j + 3], W[4 * j + 3]);
            o3 = fmaf(W[4 * j + 3], qh[4 * j + 3], o3);
            acc[4 * j + 3] += kh[4 * j + 3];
            d3 = fmaf(acc[4 * j + 3], qh[4 * j + 3], d3);
        }
        float op = (o0 + o1) + (o2 + o3);
        float dp = (d0 + d1) + (d2 + d3);
        float outv = op + __shfl_xor_sync(0xffffffffu, op, 1);
        float den  = dp + __shfl_xor_sync(0xffffffffu, dp, 1);

        if (half == 0) {
            g_lo[((size_t)t * BSZ + b) * DM + hd * DH + row] =
                SCALEF * outv / (den + EPSF);
        }
    }
}

// ---------------- residual + LayerNorm, 1 block per row -----------------------
__global__ __launch_bounds__(256) void k_ln(const float* __restrict__ hin,
                                            const float* __restrict__ gamma,
                                            const float* __restrict__ beta,
                                            float* __restrict__ out) {
    int m = blockIdx.x;
    int tid = threadIdx.x;
    const float* ar = g_qkvb + (size_t)m * DM;   // attn result (reused buffer)
    const float* hr = hin + (size_t)m * DM;

    float x[4];
    float s = 0.f;
#pragma unroll
    for (int i = 0; i < 4; i++) {
        int c = tid + i * 256;
        x[i] = ar[c] + hr[c];
        s += x[i];
    }
    __shared__ float red[8];
    int wid = tid >> 5, lane = tid & 31;
#pragma unroll
    for (int o = 16; o > 0; o >>= 1) s += __shfl_xor_sync(0xffffffffu, s, o);
    if (lane == 0) red[wid] = s;
    __syncthreads();
    float tot = 0.f;
#pragma unroll
    for (int i = 0; i < 8; i++) tot += red[i];
    float mu = tot * (1.f / (float)DM);

    float v = 0.f;
#pragma unroll
    for (int i = 0; i < 4; i++) {
        float d = x[i] - mu;
        v += d * d;
    }
#pragma unroll
    for (int o = 16; o > 0; o >>= 1) v += __shfl_xor_sync(0xffffffffu, v, o);
    __syncthreads();
    if (lane == 0) red[wid] = v;
    __syncthreads();
    float vt = 0.f;
#pragma unroll
    for (int i = 0; i < 8; i++) vt += red[i];
    float rs = rsqrtf(vt * (1.f / (float)DM) + EPSF);

#pragma unroll
    for (int i = 0; i < 4; i++) {
        int c = tid + i * 256;
        out[(size_t)m * DM + c] = (x[i] - mu) * rs * gamma[c] + beta[c];
    }
}

// ---------------- launch ------------------------------------------------------
extern "C" void kernel_launch(void* const* d_in, const int* in_sizes, int n_in,
                              void* d_out, int out_size) {
    const float* h      = (const float*)d_in[0];
    const float* w_qkvb = (const float*)d_in[1];
    const float* w_o    = (const float*)d_in[2];
    const float* ln_g   = (const float*)d_in[3];
    const float* ln_b   = (const float*)d_in[4];
    float* out = (float*)d_out;

    // qkvb projection: M=8192, N=3088, K=1024
    k_gemm_qkvb<<<dim3((NQKVB + 127) / 128, M_ROWS / 128), 256>>>(h, w_qkvb);
    // split + elu/normalize/sigmoid
    k_split<<<(M_ROWS * NH) / 8, 256>>>();
    // delta-rule recurrence: 64 CTAs x 128 threads
    k_recur<<<64, 128>>>();
    // output projection: M=8192, N=1024, K=1024 (writes into g_qkvb)
    k_gemm_out<<<dim3(DM / 128, M_ROWS / 128), 256>>>(w_o);
    // residual + layernorm
    k_ln<<<M_ROWS, 256>>>(h, ln_g, ln_b, out);
}

// round 9
// speedup vs baseline: 1.0587x; 1.0587x over previous
#include <cuda_runtime.h>
#include <math.h>

#define SLEN 2048
#define BSZ 4
#define DM 1024
#define NH 16
#define DH 64
#define NQKVB 3088          // NH*(3*DH+1)
#define M_ROWS 8192         // SLEN*BSZ
#define EPSF 1e-5f
#define SCALEF 0.125f       // 1/sqrt(64)

// ---------------- scratch (static device globals; no allocation) ----------------
// g_qkvb doubles as the output-projection result buffer (qkvb dead after split).
__device__ float g_qkvb[M_ROWS * NQKVB];     // [m][3088]; later: attn [m][1024]
__device__ float g_q[64 * SLEN * DH];        // [b*16+h][l][d]
__device__ float g_k[64 * SLEN * DH];
__device__ float g_v[64 * SLEN * DH];
__device__ float g_beta[64 * SLEN];
__device__ float g_lo[M_ROWS * DM];          // layer_out in [l][b][h*d] layout

// ---------------- fp32 GEMM: C[m][n] = sum_k A[m][k] * B[n][k] ----------------
// R3 config (measured best): BM=128, BN=64, BK=16, 256 threads, 8x4 microtile,
// register-prefetch double buffering. M % 128 == 0, K % 16 == 0; N guarded.
__device__ __forceinline__ void gemm_abt_128x64(const float* __restrict__ A,
                                                const float* __restrict__ B,
                                                float* __restrict__ C,
                                                int N, int K) {
    __shared__ float As[16][132];
    __shared__ float Bs[16][68];
    const int tid = threadIdx.x;
    const int bm = blockIdx.y * 128;
    const int bn = blockIdx.x * 64;
    const int lr = tid >> 2;          // 0..63
    const int lk = (tid & 3) << 2;    // 0,4,8,12
    const int ty = tid >> 4;          // 0..15 -> 8 rows
    const int tx = tid & 15;          // 0..15 -> 4 cols

    const float* pa0 = A + (size_t)(bm + lr) * K + lk;
    const float* pa1 = A + (size_t)(bm + lr + 64) * K + lk;
    const int nb = bn + lr;
    const float* pb = B + (size_t)(nb < N ? nb : 0) * K + lk;
    const bool bvalid = (nb < N);

    float acc[8][4];
#pragma unroll
    for (int i = 0; i < 8; i++)
#pragma unroll
        for (int j = 0; j < 4; j++) acc[i][j] = 0.f;

    // prefetch tile 0 into registers
    float4 a0 = *(const float4*)(pa0);
    float4 a1 = *(const float4*)(pa1);
    float4 bv = make_float4(0.f, 0.f, 0.f, 0.f);
    if (bvalid) bv = *(const float4*)(pb);

    for (int k0 = 0; k0 < K; k0 += 16) {
        As[lk + 0][lr] = a0.x; As[lk + 1][lr] = a0.y;
        As[lk + 2][lr] = a0.z; As[lk + 3][lr] = a0.w;
        As[lk + 0][lr + 64] = a1.x; As[lk + 1][lr + 64] = a1.y;
        As[lk + 2][lr + 64] = a1.z; As[lk + 3][lr + 64] = a1.w;
        Bs[lk + 0][lr] = bv.x; Bs[lk + 1][lr] = bv.y;
        Bs[lk + 2][lr] = bv.z; Bs[lk + 3][lr] = bv.w;
        __syncthreads();

        if (k0 + 16 < K) {   // prefetch next tile; overlaps FFMA block
            a0 = *(const float4*)(pa0 + k0 + 16);
            a1 = *(const float4*)(pa1 + k0 + 16);
            if (bvalid) bv = *(const float4*)(pb + k0 + 16);
        }

#pragma unroll
        for (int kk = 0; kk < 16; kk++) {
            float4 af0 = *(const float4*)&As[kk][ty * 8];
            float4 af1 = *(const float4*)&As[kk][ty * 8 + 4];
            float4 bf  = *(const float4*)&Bs[kk][tx * 4];
            float a[8] = {af0.x, af0.y, af0.z, af0.w, af1.x, af1.y, af1.z, af1.w};
            float b[4] = {bf.x, bf.y, bf.z, bf.w};
#pragma unroll
            for (int i = 0; i < 8; i++)
#pragma unroll
                for (int j = 0; j < 4; j++) acc[i][j] = fmaf(a[i], b[j], acc[i][j]);
        }
        __syncthreads();
    }

#pragma unroll
    for (int i = 0; i < 8; i++) {
        int row = bm + ty * 8 + i;
        int col = bn + tx * 4;
        if (col + 3 < N) {
            float4 o = make_float4(acc[i][0], acc[i][1], acc[i][2], acc[i][3]);
            *(float4*)&C[(size_t)row * N + col] = o;
        } else {
#pragma unroll
            for (int j = 0; j < 4; j++)
                if (col + j < N) C[(size_t)row * N + col + j] = acc[i][j];
        }
    }
}

__global__ __launch_bounds__(256) void k_gemm_qkvb(const float* __restrict__ A,
                                                   const float* __restrict__ B) {
    gemm_abt_128x64(A, B, g_qkvb, NQKVB, DM);
}

// output projection writes into g_qkvb (reused as [m][1024])
__global__ __launch_bounds__(256) void k_gemm_out(const float* __restrict__ B) {
    gemm_abt_128x64(g_lo, B, g_qkvb, DM, DM);
}

// ---------------- split + activations: 1 warp per (token m, head) -------------
__global__ __launch_bounds__(256) void k_split() {
    int gw = (blockIdx.x * blockDim.x + threadIdx.x) >> 5;   // 0..131071
    int lane = threadIdx.x & 31;
    int m = gw >> 4;        // token row (l*4 + b)
    int hd = gw & 15;
    int l = m >> 2;
    int b = m & 3;
    const float* base = g_qkvb + (size_t)m * NQKVB + hd * 193;

    size_t oidx = ((size_t)(b * 16 + hd) * SLEN + l) * DH + lane;

    // q : elu+1 then sum-normalize over the 64 dims
    float x0 = base[lane], x1 = base[lane + 32];
    float e0 = x0 > 0.f ? x0 + 1.f : expf(x0);
    float e1 = x1 > 0.f ? x1 + 1.f : expf(x1);
    float s = e0 + e1;
#pragma unroll
    for (int o = 16; o > 0; o >>= 1) s += __shfl_xor_sync(0xffffffffu, s, o);
    float inv = 1.f / s;
    g_q[oidx] = e0 * inv;
    g_q[oidx + 32] = e1 * inv;

    // k
    x0 = base[64 + lane]; x1 = base[96 + lane];
    e0 = x0 > 0.f ? x0 + 1.f : expf(x0);
    e1 = x1 > 0.f ? x1 + 1.f : expf(x1);
    s = e0 + e1;
#pragma unroll
    for (int o = 16; o > 0; o >>= 1) s += __shfl_xor_sync(0xffffffffu, s, o);
    inv = 1.f / s;
    g_k[oidx] = e0 * inv;
    g_k[oidx + 32] = e1 * inv;

    // v
    g_v[oidx] = base[128 + lane];
    g_v[oidx + 32] = base[160 + lane];

    // beta (sigmoid)
    if (lane == 0) {
        float br = base[192];
        g_beta[(size_t)(b * 16 + hd) * SLEN + l] = 1.f / (1.f + expf(-br));
    }
}

// ---------------- delta-rule recurrence: 1 CTA per (b,h), 128 threads ---------
// Thread pair (2*row, 2*row+1) owns W row `row`; each thread holds a 32-col
// half of W and of the cumsum acc in registers. Only k is cached in registers
// per step (kh[32]); q is re-read from SMEM in the fused update loop, keeping
// live registers ~<112 (no spills). Depth-2 scalar prefetch of global inputs.
__global__ __launch_bounds__(128) void k_recur() {
    const int bh = blockIdx.x;       // 0..63 = b*16 + h
    const int tid = threadIdx.x;     // 0..127
    const int row = tid >> 1;        // 0..63
    const int half = tid & 1;
    const int b = bh >> 4;
    const int hd = bh & 15;

    __shared__ __align__(16) float k_sh[64];
    __shared__ __align__(16) float q_sh[64];
    __shared__ float v_sh[64];

    float W[32], acc[32];
#pragma unroll
    for (int j = 0; j < 32; j++) { W[j] = 0.f; acc[j] = 0.f; }

    const float* __restrict__ kp = g_k + (size_t)bh * SLEN * DH;
    const float* __restrict__ qp = g_q + (size_t)bh * SLEN * DH;
    const float* __restrict__ vp = g_v + (size_t)bh * SLEN * DH;
    const float* __restrict__ bp = g_beta + (size_t)bh * SLEN;

    // depth-2 scalar prefetch (per-thread scalars: one lane of k/v or q)
    float kA = 0.f, vA = 0.f, qA = 0.f;
    float kB = 0.f, vB = 0.f, qB = 0.f;
    if (tid < 64) { kA = kp[tid]; vA = vp[tid]; kB = kp[DH + tid]; vB = vp[DH + tid]; }
    else          { qA = qp[tid - 64]; qB = qp[DH + tid - 64]; }
    float bA = bp[0], bB = bp[1];

    for (int t = 0; t < SLEN; t++) {
        if (tid < 64) { k_sh[tid] = kA; v_sh[tid] = vA; }
        else          { q_sh[tid - 64] = qA; }
        const float bc = bA;
        __syncthreads();

        // prefetch t+2 into the A slot (rotated at loop end); ~600cyc to cover
        if (t + 2 < SLEN) {
            const size_t o = (size_t)(t + 2) * DH;
            if (tid < 64) { kA = kp[o + tid]; vA = vp[o + tid]; }
            else          { qA = qp[o + tid - 64]; }
            bA = bp[t + 2];
        } else { kA = 0.f; vA = 0.f; qA = 0.f; bA = 0.f; }

        // loop 1: read k half into regs; kd partial (<acc_pre,k>), vo partial (<W,k>)
        const float4* k4 = (const float4*)(k_sh + half * 32);
        float kh[32];
        float kd0 = 0.f, kd1 = 0.f, kd2 = 0.f, kd3 = 0.f;
        float vo0 = 0.f, vo1 = 0.f, vo2 = 0.f, vo3 = 0.f;
#pragma unroll
        for (int j = 0; j < 8; j++) {
            float4 kv = k4[j];
            kh[4 * j + 0] = kv.x; kh[4 * j + 1] = kv.y;
            kh[4 * j + 2] = kv.z; kh[4 * j + 3] = kv.w;
            kd0 = fmaf(acc[4 * j + 0], kv.x, kd0);
            kd1 = fmaf(acc[4 * j + 1], kv.y, kd1);
            kd2 = fmaf(acc[4 * j + 2], kv.z, kd2);
            kd3 = fmaf(acc[4 * j + 3], kv.w, kd3);
            vo0 = fmaf(W[4 * j + 0], kv.x, vo0);
            vo1 = fmaf(W[4 * j + 1], kv.y, vo1);
            vo2 = fmaf(W[4 * j + 2], kv.z, vo2);
            vo3 = fmaf(W[4 * j + 3], kv.w, vo3);
        }
        const float vi = v_sh[row];
        float kdp = (kd0 + kd1) + (kd2 + kd3);
        float vop = (vo0 + vo1) + (vo2 + vo3);
        float kd = kdp + __shfl_xor_sync(0xffffffffu, kdp, 1);
        float vox = vop + __shfl_xor_sync(0xffffffffu, vop, 1);
        if (t == 0) kd = 1.f;
        const float s = 1.f / (kd + EPSF);
        const float ds = bc * kd * (vi - vox * s) * s;

        // loop 2: read q half from SMEM; W += ds*kh; out += W_new*q;
        //         acc += kh; den += acc_post*q   (all fused on one q read)
        const float4* q4 = (const float4*)(q_sh + half * 32);
        float o0 = 0.f, o1 = 0.f, o2 = 0.f, o3 = 0.f;
        float d0 = 0.f, d1 = 0.f, d2 = 0.f, d3 = 0.f;
#pragma unroll
        for (int j = 0; j < 8; j++) {
            float4 qv = q4[j];
            W[4 * j + 0] = fmaf(ds, kh[4 * j + 0], W[4 * j + 0]);
            o0 = fmaf(W[4 * j + 0], qv.x, o0);
            acc[4 * j + 0] += kh[4 * j + 0];
            d0 = fmaf(acc[4 * j + 0], qv.x, d0);

            W[4 * j + 1] = fmaf(ds, kh[4 * j + 1], W[4 * j + 1]);
            o1 = fmaf(W[4 * j + 1], qv.y, o1);
            acc[4 * j + 1] += kh[4 * j + 1];
            d1 = fmaf(acc[4 * j + 1], qv.y, d1);

            W[4 * j + 2] = fmaf(ds, kh[4 * j + 2], W[4 * j + 2]);
            o2 = fmaf(W[4 * j + 2], qv.z, o2);
            acc[4 * j + 2] += kh[4 * j + 2];
            d2 = fmaf(acc[4 * j + 2], qv.z, d2);

            W[4 * j + 3] = fmaf(ds, kh[4 * j + 3], W[4 * j + 3]);
            o3 = fmaf(W[4 * j + 3], qv.w, o3);
            acc[4 * j + 3] += kh[4 * j + 3];
            d3 = fmaf(acc[4 * j + 3], qv.w, d3);
        }
        float op = (o0 + o1) + (o2 + o3);
        float dp = (d0 + d1) + (d2 + d3);
        float outv = op + __shfl_xor_sync(0xffffffffu, op, 1);
        float den  = dp + __shfl_xor_sync(0xffffffffu, dp, 1);

        if (half == 0) {
            g_lo[((size_t)t * BSZ + b) * DM + hd * DH + row] =
                SCALEF * outv / (den + EPSF);
        }
        __syncthreads();   // all reads of k_sh/q_sh/v_sh done before next write

        // rotate prefetch pipeline: B -> current, A(t+2 load) -> B
        float kt = kB, vt = vB, qt = qB, bt = bB;
        kB = kA; vB = vA; qB = qA; bB = bA;
        kA = kt; vA = vt; qA = qt; bA = bt;
    }
}

// ---------------- residual + LayerNorm, 1 block per row -----------------------
__global__ __launch_bounds__(256) void k_ln(const float* __restrict__ hin,
                                            const float* __restrict__ gamma,
                                            const float* __restrict__ beta,
                                            float* __restrict__ out) {
    int m = blockIdx.x;
    int tid = threadIdx.x;
    const float* ar = g_qkvb + (size_t)m * DM;   // attn result (reused buffer)
    const float* hr = hin + (size_t)m * DM;

    float x[4];
    float s = 0.f;
#pragma unroll
    for (int i = 0; i < 4; i++) {
        int c = tid + i * 256;
        x[i] = ar[c] + hr[c];
        s += x[i];
    }
    __shared__ float red[8];
    int wid = tid >> 5, lane = tid & 31;
#pragma unroll
    for (int o = 16; o > 0; o >>= 1) s += __shfl_xor_sync(0xffffffffu, s, o);
    if (lane == 0) red[wid] = s;
    __syncthreads();
    float tot = 0.f;
#pragma unroll
    for (int i = 0; i < 8; i++) tot += red[i];
    float mu = tot * (1.f / (float)DM);

    float v = 0.f;
#pragma unroll
    for (int i = 0; i < 4; i++) {
        float d = x[i] - mu;
        v += d * d;
    }
#pragma unroll
    for (int o = 16; o > 0; o >>= 1) v += __shfl_xor_sync(0xffffffffu, v, o);
    __syncthreads();
    if (lane == 0) red[wid] = v;
    __syncthreads();
    float vt = 0.f;
#pragma unroll
    for (int i = 0; i < 8; i++) vt += red[i];
    float rs = rsqrtf(vt * (1.f / (float)DM) + EPSF);

#pragma unroll
    for (int i = 0; i < 4; i++) {
        int c = tid + i * 256;
        out[(size_t)m * DM + c] = (x[i] - mu) * rs * gamma[c] + beta[c];
    }
}

// ---------------- launch ------------------------------------------------------
extern "C" void kernel_launch(void* const* d_in, const int* in_sizes, int n_in,
                              void* d_out, int out_size) {
    const float* h      = (const float*)d_in[0];
    const float* w_qkvb = (const float*)d_in[1];
    const float* w_o    = (const float*)d_in[2];
    const float* ln_g   = (const float*)d_in[3];
    const float* ln_b   = (const float*)d_in[4];
    float* out = (float*)d_out;

    // qkvb projection: M=8192, N=3088, K=1024
    k_gemm_qkvb<<<dim3((NQKVB + 63) / 64, M_ROWS / 128), 256>>>(h, w_qkvb);
    // split + elu/normalize/sigmoid
    k_split<<<(M_ROWS * NH) / 8, 256>>>();
    // delta-rule recurrence: 64 CTAs x 128 threads
    k_recur<<<64, 128>>>();
    // output projection: M=8192, N=1024, K=1024 (writes into g_qkvb)
    k_gemm_out<<<dim3(DM / 64, M_ROWS / 128), 256>>>(w_o);
    // residual + layernorm
    k_ln<<<M_ROWS, 256>>>(h, ln_g, ln_b, out);
}

// round 10
// speedup vs baseline: 1.4812x; 1.3991x over previous
#include <cuda_runtime.h>
#include <math.h>

#define SLEN 2048
#define BSZ 4
#define DM 1024
#define NH 16
#define DH 64
#define NQKVB 3088          // NH*(3*DH+1)
#define M_ROWS 8192         // SLEN*BSZ
#define EPSF 1e-5f
#define SCALEF 0.125f       // 1/sqrt(64)
#define NCHUNK 32           // 2048 / 64

// ---------------- scratch (static device globals; no allocation) ----------------
__device__ float g_qkvb[M_ROWS * NQKVB];     // [m][3088]; later: attn [m][1024]
__device__ float g_q[64 * SLEN * DH];        // [b*16+h][l][d]
__device__ float g_k[64 * SLEN * DH];        // raw k, then k~ in place
__device__ float g_v[64 * SLEN * DH];
__device__ float g_beta[64 * SLEN];          // sigmoid beta, then beta' in place
__device__ float g_lo[M_ROWS * DM];          // layer_out in [l][b][h*d] layout
__device__ float g_csum[64 * NCHUNK * 64];   // per-chunk k sums
__device__ float g_acc0[64 * NCHUNK * 64];   // exclusive chunk-prefix cumsum
__device__ float g_kd[64 * SLEN];            // key_denom per token
__device__ float g_dinv[64 * SLEN];          // SCALE/(denominator+eps)
__device__ float g_M[64 * NCHUNK * 64 * 64]; // per-chunk inverse triangular
__device__ float g_S[64 * NCHUNK * 64 * 64]; // per-chunk tril(Q K~^T)

// ---------------- fp32 GEMM: C[m][n] = sum_k A[m][k] * B[n][k] ----------------
__device__ __forceinline__ void gemm_abt_128x64(const float* __restrict__ A,
                                                const float* __restrict__ B,
                                                float* __restrict__ C,
                                                int N, int K) {
    __shared__ float As[16][132];
    __shared__ float Bs[16][68];
    const int tid = threadIdx.x;
    const int bm = blockIdx.y * 128;
    const int bn = blockIdx.x * 64;
    const int lr = tid >> 2;
    const int lk = (tid & 3) << 2;
    const int ty = tid >> 4;
    const int tx = tid & 15;

    const float* pa0 = A + (size_t)(bm + lr) * K + lk;
    const float* pa1 = A + (size_t)(bm + lr + 64) * K + lk;
    const int nb = bn + lr;
    const float* pb = B + (size_t)(nb < N ? nb : 0) * K + lk;
    const bool bvalid = (nb < N);

    float acc[8][4];
#pragma unroll
    for (int i = 0; i < 8; i++)
#pragma unroll
        for (int j = 0; j < 4; j++) acc[i][j] = 0.f;

    float4 a0 = *(const float4*)(pa0);
    float4 a1 = *(const float4*)(pa1);
    float4 bv = make_float4(0.f, 0.f, 0.f, 0.f);
    if (bvalid) bv = *(const float4*)(pb);

    for (int k0 = 0; k0 < K; k0 += 16) {
        As[lk + 0][lr] = a0.x; As[lk + 1][lr] = a0.y;
        As[lk + 2][lr] = a0.z; As[lk + 3][lr] = a0.w;
        As[lk + 0][lr + 64] = a1.x; As[lk + 1][lr + 64] = a1.y;
        As[lk + 2][lr + 64] = a1.z; As[lk + 3][lr + 64] = a1.w;
        Bs[lk + 0][lr] = bv.x; Bs[lk + 1][lr] = bv.y;
        Bs[lk + 2][lr] = bv.z; Bs[lk + 3][lr] = bv.w;
        __syncthreads();

        if (k0 + 16 < K) {
            a0 = *(const float4*)(pa0 + k0 + 16);
            a1 = *(const float4*)(pa1 + k0 + 16);
            if (bvalid) bv = *(const float4*)(pb + k0 + 16);
        }

#pragma unroll
        for (int kk = 0; kk < 16; kk++) {
            float4 af0 = *(const float4*)&As[kk][ty * 8];
            float4 af1 = *(const float4*)&As[kk][ty * 8 + 4];
            float4 bf  = *(const float4*)&Bs[kk][tx * 4];
            float a[8] = {af0.x, af0.y, af0.z, af0.w, af1.x, af1.y, af1.z, af1.w};
            float b[4] = {bf.x, bf.y, bf.z, bf.w};
#pragma unroll
            for (int i = 0; i < 8; i++)
#pragma unroll
                for (int j = 0; j < 4; j++) acc[i][j] = fmaf(a[i], b[j], acc[i][j]);
        }
        __syncthreads();
    }

#pragma unroll
    for (int i = 0; i < 8; i++) {
        int row = bm + ty * 8 + i;
        int col = bn + tx * 4;
        if (col + 3 < N) {
            *(float4*)&C[(size_t)row * N + col] =
                make_float4(acc[i][0], acc[i][1], acc[i][2], acc[i][3]);
        } else {
#pragma unroll
            for (int j = 0; j < 4; j++)
                if (col + j < N) C[(size_t)row * N + col + j] = acc[i][j];
        }
    }
}

__global__ __launch_bounds__(256) void k_gemm_qkvb(const float* __restrict__ A,
                                                   const float* __restrict__ B) {
    gemm_abt_128x64(A, B, g_qkvb, NQKVB, DM);
}

__global__ __launch_bounds__(256) void k_gemm_out(const float* __restrict__ B) {
    gemm_abt_128x64(g_lo, B, g_qkvb, DM, DM);
}

// ---------------- split + activations: 1 warp per (token m, head) -------------
__global__ __launch_bounds__(256) void k_split() {
    int gw = (blockIdx.x * blockDim.x + threadIdx.x) >> 5;
    int lane = threadIdx.x & 31;
    int m = gw >> 4;
    int hd = gw & 15;
    int l = m >> 2;
    int b = m & 3;
    const float* base = g_qkvb + (size_t)m * NQKVB + hd * 193;

    size_t oidx = ((size_t)(b * 16 + hd) * SLEN + l) * DH + lane;

    float x0 = base[lane], x1 = base[lane + 32];
    float e0 = x0 > 0.f ? x0 + 1.f : expf(x0);
    float e1 = x1 > 0.f ? x1 + 1.f : expf(x1);
    float s = e0 + e1;
#pragma unroll
    for (int o = 16; o > 0; o >>= 1) s += __shfl_xor_sync(0xffffffffu, s, o);
    float inv = 1.f / s;
    g_q[oidx] = e0 * inv;
    g_q[oidx + 32] = e1 * inv;

    x0 = base[64 + lane]; x1 = base[96 + lane];
    e0 = x0 > 0.f ? x0 + 1.f : expf(x0);
    e1 = x1 > 0.f ? x1 + 1.f : expf(x1);
    s = e0 + e1;
#pragma unroll
    for (int o = 16; o > 0; o >>= 1) s += __shfl_xor_sync(0xffffffffu, s, o);
    inv = 1.f / s;
    g_k[oidx] = e0 * inv;
    g_k[oidx + 32] = e1 * inv;

    g_v[oidx] = base[128 + lane];
    g_v[oidx + 32] = base[160 + lane];

    if (lane == 0) {
        float br = base[192];
        g_beta[(size_t)(b * 16 + hd) * SLEN + l] = 1.f / (1.f + expf(-br));
    }
}

// ---------------- chunk sums of raw k ------------------------------------------
__global__ __launch_bounds__(64) void k_csum() {
    const int bid = blockIdx.x;          // bh*32 + chunk
    const int d = threadIdx.x;
    const float* base = g_k + (size_t)bid * 64 * 64 + d;
    float s = 0.f;
#pragma unroll 8
    for (int t = 0; t < 64; t++) s += base[t * 64];
    g_csum[(size_t)bid * 64 + d] = s;
}

// ---------------- exclusive scan of chunk sums ---------------------------------
__global__ __launch_bounds__(64) void k_scan() {
    const int bh = blockIdx.x;
    const int d = threadIdx.x;
    float v[NCHUNK];
#pragma unroll
    for (int c = 0; c < NCHUNK; c++)
        v[c] = g_csum[((size_t)bh * NCHUNK + c) * 64 + d];
    float a = 0.f;
#pragma unroll
    for (int c = 0; c < NCHUNK; c++) {
        g_acc0[((size_t)bh * NCHUNK + c) * 64 + d] = a;
        a += v[c];
    }
}

// ---------------- per-chunk K-side precompute ----------------------------------
// G = K K^T (raw); kd_t = <acc0,k_t> + sum_{s<t} G[t][s]; k~ = k/(kd+eps),
// beta' = beta*kd (in place); M = (I + diag(beta') Atril)^-1 via forward subst.
__global__ __launch_bounds__(256) void k_prep_k() {
    const int bid = blockIdx.x;          // bh*32 + c
    const int bh = bid >> 5, c = bid & 31;
    __shared__ float Ks[64 * 68];
    __shared__ float Gs[64 * 68];
    __shared__ float acc0s[64], bprs[64], invs[64], tmp[64];
    const int tid = threadIdx.x;
    const int r = tid >> 2, q = tid & 3;

    {
        const float* kg = g_k + ((size_t)bid * 64 + r) * 64 + q * 16;
#pragma unroll
        for (int i = 0; i < 4; i++)
            *(float4*)&Ks[r * 68 + q * 16 + i * 4] = *(const float4*)(kg + i * 4);
    }
    if (tid < 64) acc0s[tid] = g_acc0[(size_t)bid * 64 + tid];
    __syncthreads();

    const int tr = (tid >> 4) << 2, tc = (tid & 15) << 2;
    {   // G = K K^T
        float acc[4][4];
#pragma unroll
        for (int x = 0; x < 4; x++)
#pragma unroll
            for (int y = 0; y < 4; y++) acc[x][y] = 0.f;
        for (int j = 0; j < 64; j += 4) {
            float a[4][4], b[4][4];
#pragma unroll
            for (int x = 0; x < 4; x++) {
                float4 t4 = *(const float4*)&Ks[(tr + x) * 68 + j];
                a[x][0] = t4.x; a[x][1] = t4.y; a[x][2] = t4.z; a[x][3] = t4.w;
            }
#pragma unroll
            for (int y = 0; y < 4; y++) {
                float4 t4 = *(const float4*)&Ks[(tc + y) * 68 + j];
                b[y][0] = t4.x; b[y][1] = t4.y; b[y][2] = t4.z; b[y][3] = t4.w;
            }
#pragma unroll
            for (int x = 0; x < 4; x++)
#pragma unroll
                for (int y = 0; y < 4; y++)
#pragma unroll
                    for (int m = 0; m < 4; m++)
                        acc[x][y] = fmaf(a[x][m], b[y][m], acc[x][y]);
        }
#pragma unroll
        for (int x = 0; x < 4; x++)
            *(float4*)&Gs[(tr + x) * 68 + tc] =
                make_float4(acc[x][0], acc[x][1], acc[x][2], acc[x][3]);
    }
    __syncthreads();

    if (tid < 64) {
        const int t = tid;
        float kd = 0.f;
        const float* krow = &Ks[t * 68];
        for (int d = 0; d < 64; d++) kd = fmaf(acc0s[d], krow[d], kd);
        const float* grow = &Gs[t * 68];
        for (int s = 0; s < t; s++) kd += grow[s];
        if (c == 0 && t == 0) kd = 1.f;
        invs[t] = 1.f / (kd + EPSF);
        const size_t gi = (size_t)bh * SLEN + c * 64 + t;
        const float braw = g_beta[gi];
        bprs[t] = braw * kd;
        g_beta[gi] = braw * kd;
        g_kd[gi] = kd;
    }
    __syncthreads();

    {   // write k~ in place
        const float inv = invs[r];
        float* ko = g_k + ((size_t)bid * 64 + r) * 64 + q * 16;
#pragma unroll
        for (int i = 0; i < 16; i += 4) {
            float4 x = *(const float4*)&Ks[r * 68 + q * 16 + i];
            x.x *= inv; x.y *= inv; x.z *= inv; x.w *= inv;
            *(float4*)(ko + i) = x;
        }
    }

    // forward substitution in place: Gs rows become M rows
    if (tid < 64) Gs[tid] = (tid == 0) ? 1.f : 0.f;
    __syncthreads();
    for (int t = 1; t < 64; t++) {
        if (tid < 64)
            tmp[tid] = (tid < t) ? bprs[t] * invs[t] * Gs[t * 68 + tid] * invs[tid]
                                 : 0.f;
        __syncthreads();
        if (tid < 64) {
            const int j = tid;
            float val = (j == t) ? 1.f : 0.f;
            for (int s = 0; s < t; s++) val = fmaf(-tmp[s], Gs[s * 68 + j], val);
            Gs[t * 68 + j] = val;
        }
        __syncthreads();
    }

    {   // write M
        float* mo = g_M + (size_t)bid * 4096 + r * 64 + q * 16;
#pragma unroll
        for (int i = 0; i < 4; i++)
            *(float4*)(mo + i * 4) = *(const float4*)&Gs[r * 68 + q * 16 + i * 4];
    }
}

// ---------------- per-chunk Q-side precompute ----------------------------------
// S = incl-tril(Q K~^T); den_t = <acc0,q_t> + sum_{s<=t} S[t,s]*(kd_s+eps)
__global__ __launch_bounds__(256) void k_prep_q() {
    const int bid = blockIdx.x;
    const int bh = bid >> 5, c = bid & 31;
    __shared__ float Qs[64 * 68];
    __shared__ float Ks[64 * 68];
    __shared__ float acc0s[64], kdws[64];
    __shared__ float denp[64][17];
    const int tid = threadIdx.x;
    const int r = tid >> 2, q = tid & 3;

    {
        const float* qg = g_q + ((size_t)bid * 64 + r) * 64 + q * 16;
        const float* kg = g_k + ((size_t)bid * 64 + r) * 64 + q * 16;
#pragma unroll
        for (int i = 0; i < 4; i++) {
            *(float4*)&Qs[r * 68 + q * 16 + i * 4] = *(const float4*)(qg + i * 4);
            *(float4*)&Ks[r * 68 + q * 16 + i * 4] = *(const float4*)(kg + i * 4);
        }
    }
    if (tid < 64) {
        acc0s[tid] = g_acc0[(size_t)bid * 64 + tid];
        kdws[tid] = g_kd[(size_t)bh * SLEN + c * 64 + tid] + EPSF;
    }
    __syncthreads();

    const int tr = (tid >> 4) << 2, tc = (tid & 15) << 2;
    float p[4][4];
#pragma unroll
    for (int x = 0; x < 4; x++)
#pragma unroll
        for (int y = 0; y < 4; y++) p[x][y] = 0.f;
    for (int j = 0; j < 64; j += 4) {
        float a[4][4], b[4][4];
#pragma unroll
        for (int x = 0; x < 4; x++) {
            float4 t4 = *(const float4*)&Qs[(tr + x) * 68 + j];
            a[x][0] = t4.x; a[x][1] = t4.y; a[x][2] = t4.z; a[x][3] = t4.w;
        }
#pragma unroll
        for (int y = 0; y < 4; y++) {
            float4 t4 = *(const float4*)&Ks[(tc + y) * 68 + j];
            b[y][0] = t4.x; b[y][1] = t4.y; b[y][2] = t4.z; b[y][3] = t4.w;
        }
#pragma unroll
        for (int x = 0; x < 4; x++)
#pragma unroll
            for (int y = 0; y < 4; y++)
#pragma unroll
                for (int m = 0; m < 4; m++)
                    p[x][y] = fmaf(a[x][m], b[y][m], p[x][y]);
    }
#pragma unroll
    for (int x = 0; x < 4; x++) {
        const int t = tr + x;
        float4 sv;
        sv.x = (tc + 0 <= t) ? p[x][0] : 0.f;
        sv.y = (tc + 1 <= t) ? p[x][1] : 0.f;
        sv.z = (tc + 2 <= t) ? p[x][2] : 0.f;
        sv.w = (tc + 3 <= t) ? p[x][3] : 0.f;
        *(float4*)(g_S + (size_t)bid * 4096 + t * 64 + tc) = sv;
        denp[t][tid & 15] = sv.x * kdws[tc + 0] + sv.y * kdws[tc + 1] +
                            sv.z * kdws[tc + 2] + sv.w * kdws[tc + 3];
    }
    __syncthreads();
    if (tid < 64) {
        const int t = tid;
        float den = 0.f;
#pragma unroll
        for (int g = 0; g < 16; g++) den += denp[t][g];
        const float* qrow = &Qs[t * 68];
        for (int d = 0; d < 64; d++) den = fmaf(acc0s[d], qrow[d], den);
        g_dinv[(size_t)bh * SLEN + c * 64 + t] = SCALEF / (den + EPSF);
    }
}

// ---------------- sequential chunk recurrence ----------------------------------
// grid (2, 64): blockIdx.y = bh, blockIdx.x = value-dim half. 256 threads.
// Per chunk: rhs = diag(b')(V - K~ W^T); U = M rhs; Out = (Q W^T + S U)*dinv;
// W += U^T K~.   W kept transposed in SMEM: Wt[j][i-half].
__global__ __launch_bounds__(256) void k_recur_chunk() {
    extern __shared__ float sm[];
    const int ih = blockIdx.x;
    const int bh = blockIdx.y;
    const int tid = threadIdx.x;
    float* Kc = sm;                 // 64 x 68
    float* Mc = sm + 4352;
    float* Qc = sm + 8704;
    float* Sc = sm + 13056;
    float* Wt = sm + 17408;         // 64 x 36  (j-major, i-half cols)
    float* Vc = sm + 19712;         // 64 x 36  (t-major, i-half cols)
    float* Rc = sm + 22016;
    float* Uc = sm + 24320;
    float* bpr = sm + 26624;
    float* dv  = sm + 26688;

    for (int i = tid; i < 2304; i += 256) Wt[i] = 0.f;

    const int r = tid >> 2, q = tid & 3;
    const int tr = (tid >> 4) << 2;      // 4 t-rows (or j-rows in G4)
    const int ic = (tid & 15) << 1;      // 2 i-cols
    const int b_ = bh >> 4;
    const int hd = bh & 15;

    for (int c = 0; c < NCHUNK; c++) {
        __syncthreads();   // prior chunk fully done before overwriting buffers
        {
            const size_t row = ((size_t)bh * NCHUNK + c) * 64 + r;
            const float* kg = g_k + row * 64 + q * 16;
            const float* qg = g_q + row * 64 + q * 16;
            const size_t ms = ((size_t)bh * NCHUNK + c) * 4096 + r * 64 + q * 16;
#pragma unroll
            for (int i = 0; i < 4; i++) {
                *(float4*)&Kc[r * 68 + q * 16 + i * 4] = *(const float4*)(kg + i * 4);
                *(float4*)&Qc[r * 68 + q * 16 + i * 4] = *(const float4*)(qg + i * 4);
                *(float4*)&Mc[r * 68 + q * 16 + i * 4] = *(const float4*)(g_M + ms + i * 4);
                *(float4*)&Sc[r * 68 + q * 16 + i * 4] = *(const float4*)(g_S + ms + i * 4);
            }
            const float* vg = g_v + row * 64 + ih * 32 + q * 8;
            *(float4*)&Vc[r * 36 + q * 8]     = *(const float4*)(vg);
            *(float4*)&Vc[r * 36 + q * 8 + 4] = *(const float4*)(vg + 4);
            if (tid < 64) {
                bpr[tid] = g_beta[(size_t)bh * SLEN + c * 64 + tid];
                dv[tid]  = g_dinv[(size_t)bh * SLEN + c * 64 + tid];
            }
        }
        __syncthreads();

        // G1: Rc[t][i] = bpr[t]*(Vc[t][i] - sum_j Kc[t][j]*Wt[j][i])
        {
            float acc[4][2];
#pragma unroll
            for (int x = 0; x < 4; x++) { acc[x][0] = 0.f; acc[x][1] = 0.f; }
            for (int j = 0; j < 64; j += 4) {
                float a[4][4], w[4][2];
#pragma unroll
                for (int x = 0; x < 4; x++) {
                    float4 t4 = *(const float4*)&Kc[(tr + x) * 68 + j];
                    a[x][0] = t4.x; a[x][1] = t4.y; a[x][2] = t4.z; a[x][3] = t4.w;
                }
#pragma unroll
                for (int m = 0; m < 4; m++) {
                    float2 t2 = *(const float2*)&Wt[(j + m) * 36 + ic];
                    w[m][0] = t2.x; w[m][1] = t2.y;
                }
#pragma unroll
                for (int x = 0; x < 4; x++)
#pragma unroll
                    for (int m = 0; m < 4; m++) {
                        acc[x][0] = fmaf(a[x][m], w[m][0], acc[x][0]);
                        acc[x][1] = fmaf(a[x][m], w[m][1], acc[x][1]);
                    }
            }
#pragma unroll
            for (int x = 0; x < 4; x++) {
                const int t = tr + x;
                const float bb = bpr[t];
                float2 vv = *(const float2*)&Vc[t * 36 + ic];
                float2 rr;
                rr.x = bb * (vv.x - acc[x][0]);
                rr.y = bb * (vv.y - acc[x][1]);
                *(float2*)&Rc[t * 36 + ic] = rr;
            }
        }
        __syncthreads();

        // G2: Uc[t][i] = sum_s Mc[t][s]*Rc[s][i]
        {
            float acc[4][2];
#pragma unroll
            for (int x = 0; x < 4; x++) { acc[x][0] = 0.f; acc[x][1] = 0.f; }
            for (int s = 0; s < 64; s += 4) {
                float a[4][4], bm[4][2];
#pragma unroll
                for (int x = 0; x < 4; x++) {
                    float4 t4 = *(const float4*)&Mc[(tr + x) * 68 + s];
                    a[x][0] = t4.x; a[x][1] = t4.y; a[x][2] = t4.z; a[x][3] = t4.w;
                }
#pragma unroll
                for (int m = 0; m < 4; m++) {
                    float2 t2 = *(const float2*)&Rc[(s + m) * 36 + ic];
                    bm[m][0] = t2.x; bm[m][1] = t2.y;
                }
#pragma unroll
                for (int x = 0; x < 4; x++)
#pragma unroll
                    for (int m = 0; m < 4; m++) {
                        acc[x][0] = fmaf(a[x][m], bm[m][0], acc[x][0]);
                        acc[x][1] = fmaf(a[x][m], bm[m][1], acc[x][1]);
                    }
            }
#pragma unroll
            for (int x = 0; x < 4; x++)
                *(float2*)&Uc[(tr + x) * 36 + ic] =
                    make_float2(acc[x][0], acc[x][1]);
        }
        __syncthreads();

        // G3: Out[t][i] = (sum_j Qc[t][j]*Wt[j][i] + sum_s Sc[t][s]*Uc[s][i])*dv[t]
        {
            float acc[4][2];
#pragma unroll
            for (int x = 0; x < 4; x++) { acc[x][0] = 0.f; acc[x][1] = 0.f; }
            for (int j = 0; j < 64; j += 4) {
                float a[4][4], w[4][2];
#pragma unroll
                for (int x = 0; x < 4; x++) {
                    float4 t4 = *(const float4*)&Qc[(tr + x) * 68 + j];
                    a[x][0] = t4.x; a[x][1] = t4.y; a[x][2] = t4.z; a[x][3] = t4.w;
                }
#pragma unroll
                for (int m = 0; m < 4; m++) {
                    float2 t2 = *(const float2*)&Wt[(j + m) * 36 + ic];
                    w[m][0] = t2.x; w[m][1] = t2.y;
                }
#pragma unroll
                for (int x = 0; x < 4; x++)
#pragma unroll
                    for (int m = 0; m < 4; m++) {
                        acc[x][0] = fmaf(a[x][m], w[m][0], acc[x][0]);
                        acc[x][1] = fmaf(a[x][m], w[m][1], acc[x][1]);
                    }
            }
            for (int s = 0; s < 64; s += 4) {
                float a[4][4], bm[4][2];
#pragma unroll
                for (int x = 0; x < 4; x++) {
                    float4 t4 = *(const float4*)&Sc[(tr + x) * 68 + s];
                    a[x][0] = t4.x; a[x][1] = t4.y; a[x][2] = t4.z; a[x][3] = t4.w;
                }
#pragma unroll
                for (int m = 0; m < 4; m++) {
                    float2 t2 = *(const float2*)&Uc[(s + m) * 36 + ic];
                    bm[m][0] = t2.x; bm[m][1] = t2.y;
                }
#pragma unroll
                for (int x = 0; x < 4; x++)
#pragma unroll
                    for (int m = 0; m < 4; m++) {
                        acc[x][0] = fmaf(a[x][m], bm[m][0], acc[x][0]);
                        acc[x][1] = fmaf(a[x][m], bm[m][1], acc[x][1]);
                    }
            }
#pragma unroll
            for (int x = 0; x < 4; x++) {
                const int t = tr + x;
                const float sc = dv[t];
                const size_t o = ((size_t)(c * 64 + t) * BSZ + b_) * DM +
                                 hd * 64 + ih * 32 + ic;
                *(float2*)&g_lo[o] = make_float2(acc[x][0] * sc, acc[x][1] * sc);
            }
        }
        __syncthreads();

        // G4: Wt[j][i] += sum_t Uc[t][i]*Kc[t][j]   (thread tile: 4 j x 2 i)
        {
            float acc[4][2];
#pragma unroll
            for (int x = 0; x < 4; x++) { acc[x][0] = 0.f; acc[x][1] = 0.f; }
#pragma unroll 8
            for (int t = 0; t < 64; t++) {
                float4 kv = *(const float4*)&Kc[t * 68 + tr];
                float2 uv = *(const float2*)&Uc[t * 36 + ic];
                acc[0][0] = fmaf(kv.x, uv.x, acc[0][0]);
                acc[0][1] = fmaf(kv.x, uv.y, acc[0][1]);
                acc[1][0] = fmaf(kv.y, uv.x, acc[1][0]);
                acc[1][1] = fmaf(kv.y, uv.y, acc[1][1]);
                acc[2][0] = fmaf(kv.z, uv.x, acc[2][0]);
                acc[2][1] = fmaf(kv.z, uv.y, acc[2][1]);
                acc[3][0] = fmaf(kv.w, uv.x, acc[3][0]);
                acc[3][1] = fmaf(kv.w, uv.y, acc[3][1]);
            }
#pragma unroll
            for (int x = 0; x < 4; x++) {
                float2 wv = *(const float2*)&Wt[(tr + x) * 36 + ic];
                wv.x += acc[x][0];
                wv.y += acc[x][1];
                *(float2*)&Wt[(tr + x) * 36 + ic] = wv;
            }
        }
    }
}

// ---------------- residual + LayerNorm, 1 block per row -----------------------
__global__ __launch_bounds__(256) void k_ln(const float* __restrict__ hin,
                                            const float* __restrict__ gamma,
                                            const float* __restrict__ beta,
                                            float* __restrict__ out) {
    int m = blockIdx.x;
    int tid = threadIdx.x;
    const float* ar = g_qkvb + (size_t)m * DM;
    const float* hr = hin + (size_t)m * DM;

    float x[4];
    float s = 0.f;
#pragma unroll
    for (int i = 0; i < 4; i++) {
        int c = tid + i * 256;
        x[i] = ar[c] + hr[c];
        s += x[i];
    }
    __shared__ float red[8];
    int wid = tid >> 5, lane = tid & 31;
#pragma unroll
    for (int o = 16; o > 0; o >>= 1) s += __shfl_xor_sync(0xffffffffu, s, o);
    if (lane == 0) red[wid] = s;
    __syncthreads();
    float tot = 0.f;
#pragma unroll
    for (int i = 0; i < 8; i++) tot += red[i];
    float mu = tot * (1.f / (float)DM);

    float v = 0.f;
#pragma unroll
    for (int i = 0; i < 4; i++) {
        float d = x[i] - mu;
        v += d * d;
    }
#pragma unroll
    for (int o = 16; o > 0; o >>= 1) v += __shfl_xor_sync(0xffffffffu, v, o);
    __syncthreads();
    if (lane == 0) red[wid] = v;
    __syncthreads();
    float vt = 0.f;
#pragma unroll
    for (int i = 0; i < 8; i++) vt += red[i];
    float rs = rsqrtf(vt * (1.f / (float)DM) + EPSF);

#pragma unroll
    for (int i = 0; i < 4; i++) {
        int c = tid + i * 256;
        out[(size_t)m * DM + c] = (x[i] - mu) * rs * gamma[c] + beta[c];
    }
}

// ---------------- launch ------------------------------------------------------
extern "C" void kernel_launch(void* const* d_in, const int* in_sizes, int n_in,
                              void* d_out, int out_size) {
    const float* h      = (const float*)d_in[0];
    const float* w_qkvb = (const float*)d_in[1];
    const float* w_o    = (const float*)d_in[2];
    const float* ln_g   = (const float*)d_in[3];
    const float* ln_b   = (const float*)d_in[4];
    float* out = (float*)d_out;

    const int k5_smem = 26752 * 4;   // 107008 bytes
    cudaFuncSetAttribute(k_recur_chunk,
                         cudaFuncAttributeMaxDynamicSharedMemorySize, 110592);

    k_gemm_qkvb<<<dim3((NQKVB + 63) / 64, M_ROWS / 128), 256>>>(h, w_qkvb);
    k_split<<<(M_ROWS * NH) / 8, 256>>>();
    k_csum<<<64 * NCHUNK, 64>>>();
    k_scan<<<64, 64>>>();
    k_prep_k<<<64 * NCHUNK, 256>>>();
    k_prep_q<<<64 * NCHUNK, 256>>>();
    k_recur_chunk<<<dim3(2, 64), 256, k5_smem>>>();
    k_gemm_out<<<dim3(DM / 64, M_ROWS / 128), 256>>>(w_o);
    k_ln<<<M_ROWS, 256>>>(h, ln_g, ln_b, out);
}

// round 14
// speedup vs baseline: 2.2207x; 1.4992x over previous
#include <cuda_runtime.h>
#include <cuda_bf16.h>
#include <math.h>

#define SLEN 2048
#define BSZ 4
#define DM 1024
#define NH 16
#define DH 64
#define NQKVB 3088          // NH*(3*DH+1)
#define M_ROWS 8192         // SLEN*BSZ
#define EPSF 1e-5f
#define SCALEF 0.125f       // 1/sqrt(64)
#define NCHUNK 32           // 2048 / 64
#define KW 512              // K/2 = bf16x2 words per row (K = 1024)

// ---------------- scratch (static device globals; no allocation) ----------------
__device__ float g_qkvb[M_ROWS * NQKVB];     // [m][3088]; later: attn [m][1024]
__device__ float g_q[64 * SLEN * DH];        // [b*16+h][l][d]
__device__ float g_k[64 * SLEN * DH];        // raw k, then k~ in place
__device__ float g_v[64 * SLEN * DH];
__device__ float g_beta[64 * SLEN];          // sigmoid beta, then beta' in place
__device__ float g_lo[M_ROWS * DM];          // layer_out in [l][b][h*d] layout
__device__ float g_csum[64 * NCHUNK * 64];
__device__ float g_acc0[64 * NCHUNK * 64];
__device__ float g_kd[64 * SLEN];
__device__ float g_dinv[64 * SLEN];
__device__ float g_M[64 * NCHUNK * 64 * 64];
__device__ float g_S[64 * NCHUNK * 64 * 64];
// bf16-split staging (k-pair-permuted): A side sized for M_ROWS, B side for NQKVB
__device__ unsigned g_Ah[M_ROWS * KW];
__device__ unsigned g_Al[M_ROWS * KW];
__device__ unsigned g_Bh[NQKVB * KW];
__device__ unsigned g_Bl[NQKVB * KW];

// ---------------- split fp32 -> (bf16 hi, bf16 lo), k-pair permuted -----------
// X: [R][1024] fp32. Out: [R][512] u32 words; within each 16-col group the
// pair order is [0,4,1,5,2,6,3,7] so a GEMM thread's LDS.64 at offset 2t yields
// pairs (t, t+4) = the m16n8k16 fragment k-positions {2t,2t+1,2t+8,2t+9}.
__global__ __launch_bounds__(256) void k_split16(const float* __restrict__ X,
                                                 unsigned* __restrict__ Hh,
                                                 unsigned* __restrict__ Hl) {
    const size_t idx = (size_t)blockIdx.x * 256 + threadIdx.x;  // one float4
    const size_t row = idx >> 8;
    const int k0 = (int)(idx & 255) << 2;
    float4 x = *(const float4*)&X[row * 1024 + k0];

    __nv_bfloat16 h0 = __float2bfloat16_rn(x.x);
    __nv_bfloat16 h1 = __float2bfloat16_rn(x.y);
    __nv_bfloat16 h2 = __float2bfloat16_rn(x.z);
    __nv_bfloat16 h3 = __float2bfloat16_rn(x.w);
    float l0 = x.x - __bfloat162float(h0);
    float l1 = x.y - __bfloat162float(h1);
    float l2 = x.z - __bfloat162float(h2);
    float l3 = x.w - __bfloat162float(h3);
    __nv_bfloat16 e0 = __float2bfloat16_rn(l0);
    __nv_bfloat16 e1 = __float2bfloat16_rn(l1);
    __nv_bfloat16 e2 = __float2bfloat16_rn(l2);
    __nv_bfloat16 e3 = __float2bfloat16_rn(l3);

    unsigned hw0 = (unsigned)*(unsigned short*)&h0 |
                   ((unsigned)*(unsigned short*)&h1 << 16);
    unsigned hw1 = (unsigned)*(unsigned short*)&h2 |
                   ((unsigned)*(unsigned short*)&h3 << 16);
    unsigned lw0 = (unsigned)*(unsigned short*)&e0 |
                   ((unsigned)*(unsigned short*)&e1 << 16);
    unsigned lw1 = (unsigned)*(unsigned short*)&e2 |
                   ((unsigned)*(unsigned short*)&e3 << 16);

    const int grp = k0 >> 4;
    const int p0 = (k0 >> 1) & 7, p1 = p0 + 1;
    const int pp0 = ((p0 & 3) << 1) | (p0 >> 2);
    const int pp1 = ((p1 & 3) << 1) | (p1 >> 2);
    const size_t base = row * KW + grp * 8;
    Hh[base + pp0] = hw0; Hh[base + pp1] = hw1;
    Hl[base + pp0] = lw0; Hl[base + pp1] = lw1;
}

// ---------------- tensor-core bf16-split GEMM: C = A * B^T --------------------
// BM=128, BN=64, BK=16 (8 words), 256 threads (8 warps, 4x2), warp tile 32x32.
// D = Ah*Bh + Ah*Bl + Al*Bh in fp32 accumulators. K fixed = 1024.
__device__ __forceinline__ void mma16816(float* c, unsigned a0, unsigned a1,
                                         unsigned a2, unsigned a3,
                                         unsigned b0, unsigned b1) {
    asm volatile(
        "mma.sync.aligned.m16n8k16.row.col.f32.bf16.bf16.f32 "
        "{%0,%1,%2,%3}, {%4,%5,%6,%7}, {%8,%9}, {%0,%1,%2,%3};\n"
        : "+f"(c[0]), "+f"(c[1]), "+f"(c[2]), "+f"(c[3])
        : "r"(a0), "r"(a1), "r"(a2), "r"(a3), "r"(b0), "r"(b1));
}

__global__ __launch_bounds__(256) void k_gemm_tc(const unsigned* __restrict__ Ah,
                                                 const unsigned* __restrict__ Al,
                                                 const unsigned* __restrict__ Bh,
                                                 const unsigned* __restrict__ Bl,
                                                 float* __restrict__ C, int N) {
    __shared__ unsigned sA[2][128 * 8];   // [hi/lo][m][8 words]
    __shared__ unsigned sB[2][64 * 8];
    const int tid = threadIdx.x;
    const int bm = blockIdx.y * 128;
    const int bn = blockIdx.x * 64;

    // loaders: A 2 x uint4 per thread, B 1 x uint4
    const int arow = tid >> 1, ahalf = (tid & 1) * 4;
    const int brow = tid >> 2, bsel = tid & 3;
    const unsigned* pAh = Ah + (size_t)(bm + arow) * KW + ahalf;
    const unsigned* pAl = Al + (size_t)(bm + arow) * KW + ahalf;
    const int brg = bn + brow;
    const unsigned* pB = ((bsel & 2) ? Bl : Bh) +
                         (size_t)(brg < N ? brg : 0) * KW + (bsel & 1) * 4;

    // compute mapping
    const int w = tid >> 5, lane = tid & 31;
    const int g = lane >> 2, t = lane & 3;
    const int wm = (w >> 1) * 32, wn = (w & 1) * 32;

    float c[2][4][4];
#pragma unroll
    for (int i = 0; i < 2; i++)
#pragma unroll
        for (int j = 0; j < 4; j++)
#pragma unroll
            for (int e = 0; e < 4; e++) c[i][j][e] = 0.f;

    uint4 fa = *(const uint4*)pAh;
    uint4 fl = *(const uint4*)pAl;
    uint4 fb = *(const uint4*)pB;

    for (int k0 = 0; k0 < KW; k0 += 8) {
        *(uint4*)&sA[0][arow * 8 + ahalf] = fa;
        *(uint4*)&sA[1][arow * 8 + ahalf] = fl;
        *(uint4*)&sB[bsel >> 1][brow * 8 + (bsel & 1) * 4] = fb;
        __syncthreads();

        if (k0 + 8 < KW) {
            fa = *(const uint4*)(pAh + k0 + 8);
            fl = *(const uint4*)(pAl + k0 + 8);
            fb = *(const uint4*)(pB + k0 + 8);
        }

        // fragments
        uint2 ah[2][2], al[2][2];           // [matom][row g / g+8]
#pragma unroll
        for (int ma = 0; ma < 2; ma++) {
            const int r0 = (wm + ma * 16 + g) * 8 + 2 * t;
            const int r1 = (wm + ma * 16 + g + 8) * 8 + 2 * t;
            ah[ma][0] = *(const uint2*)&sA[0][r0];
            ah[ma][1] = *(const uint2*)&sA[0][r1];
            al[ma][0] = *(const uint2*)&sA[1][r0];
            al[ma][1] = *(const uint2*)&sA[1][r1];
        }
#pragma unroll
        for (int na = 0; na < 4; na++) {
            const int rb = (wn + na * 8 + g) * 8 + 2 * t;
            uint2 bh = *(const uint2*)&sB[0][rb];
            uint2 bl = *(const uint2*)&sB[1][rb];
#pragma unroll
            for (int ma = 0; ma < 2; ma++) {
                mma16816(c[ma][na], ah[ma][0].x, ah[ma][1].x,
                         ah[ma][0].y, ah[ma][1].y, bh.x, bh.y);
                mma16816(c[ma][na], ah[ma][0].x, ah[ma][1].x,
                         ah[ma][0].y, ah[ma][1].y, bl.x, bl.y);
                mma16816(c[ma][na], al[ma][0].x, al[ma][1].x,
                         al[ma][0].y, al[ma][1].y, bh.x, bh.y);
            }
        }
        __syncthreads();
    }

    // epilogue: c0,c1 -> (g, 2t..2t+1); c2,c3 -> (g+8, ...)
#pragma unroll
    for (int ma = 0; ma < 2; ma++) {
#pragma unroll
        for (int na = 0; na < 4; na++) {
            const int col = bn + wn + na * 8 + 2 * t;
            if (bn + wn + na * 8 < N) {   // N % 8 == 0: atom all-in or all-out
                const int r0 = bm + wm + ma * 16 + g;
                *(float2*)&C[(size_t)r0 * N + col] =
                    make_float2(c[ma][na][0], c[ma][na][1]);
                *(float2*)&C[(size_t)(r0 + 8) * N + col] =
                    make_float2(c[ma][na][2], c[ma][na][3]);
            }
        }
    }
}

// ---------------- split + activations: 1 warp per (token m, head) -------------
__global__ __launch_bounds__(256) void k_split() {
    int gw = (blockIdx.x * blockDim.x + threadIdx.x) >> 5;
    int lane = threadIdx.x & 31;
    int m = gw >> 4;
    int hd = gw & 15;
    int l = m >> 2;
    int b = m & 3;
    const float* base = g_qkvb + (size_t)m * NQKVB + hd * 193;

    size_t oidx = ((size_t)(b * 16 + hd) * SLEN + l) * DH + lane;

    float x0 = base[lane], x1 = base[lane + 32];
    float e0 = x0 > 0.f ? x0 + 1.f : expf(x0);
    float e1 = x1 > 0.f ? x1 + 1.f : expf(x1);
    float s = e0 + e1;
#pragma unroll
    for (int o = 16; o > 0; o >>= 1) s += __shfl_xor_sync(0xffffffffu, s, o);
    float inv = 1.f / s;
    g_q[oidx] = e0 * inv;
    g_q[oidx + 32] = e1 * inv;

    x0 = base[64 + lane]; x1 = base[96 + lane];
    e0 = x0 > 0.f ? x0 + 1.f : expf(x0);
    e1 = x1 > 0.f ? x1 + 1.f : expf(x1);
    s = e0 + e1;
#pragma unroll
    for (int o = 16; o > 0; o >>= 1) s += __shfl_xor_sync(0xffffffffu, s, o);
    inv = 1.f / s;
    g_k[oidx] = e0 * inv;
    g_k[oidx + 32] = e1 * inv;

    g_v[oidx] = base[128 + lane];
    g_v[oidx + 32] = base[160 + lane];

    if (lane == 0) {
        float br = base[192];
        g_beta[(size_t)(b * 16 + hd) * SLEN + l] = 1.f / (1.f + expf(-br));
    }
}

// ---------------- chunk sums of raw k ------------------------------------------
__global__ __launch_bounds__(64) void k_csum() {
    const int bid = blockIdx.x;
    const int d = threadIdx.x;
    const float* base = g_k + (size_t)bid * 64 * 64 + d;
    float s = 0.f;
#pragma unroll 8
    for (int t = 0; t < 64; t++) s += base[t * 64];
    g_csum[(size_t)bid * 64 + d] = s;
}

// ---------------- exclusive scan of chunk sums ---------------------------------
__global__ __launch_bounds__(64) void k_scan() {
    const int bh = blockIdx.x;
    const int d = threadIdx.x;
    float v[NCHUNK];
#pragma unroll
    for (int c = 0; c < NCHUNK; c++)
        v[c] = g_csum[((size_t)bh * NCHUNK + c) * 64 + d];
    float a = 0.f;
#pragma unroll
    for (int c = 0; c < NCHUNK; c++) {
        g_acc0[((size_t)bh * NCHUNK + c) * 64 + d] = a;
        a += v[c];
    }
}

// ---------------- per-chunk K-side precompute ----------------------------------
__global__ __launch_bounds__(256) void k_prep_k() {
    const int bid = blockIdx.x;
    const int bh = bid >> 5, c = bid & 31;
    __shared__ float Ks[64 * 68];
    __shared__ float Gs[64 * 68];
    __shared__ float acc0s[64], bprs[64], invs[64], tmp[64];
    const int tid = threadIdx.x;
    const int r = tid >> 2, q = tid & 3;

    {
        const float* kg = g_k + ((size_t)bid * 64 + r) * 64 + q * 16;
#pragma unroll
        for (int i = 0; i < 4; i++)
            *(float4*)&Ks[r * 68 + q * 16 + i * 4] = *(const float4*)(kg + i * 4);
    }
    if (tid < 64) acc0s[tid] = g_acc0[(size_t)bid * 64 + tid];
    __syncthreads();

    const int tr = (tid >> 4) << 2, tc = (tid & 15) << 2;
    {   // G = K K^T
        float acc[4][4];
#pragma unroll
        for (int x = 0; x < 4; x++)
#pragma unroll
            for (int y = 0; y < 4; y++) acc[x][y] = 0.f;
        for (int j = 0; j < 64; j += 4) {
            float a[4][4], b[4][4];
#pragma unroll
            for (int x = 0; x < 4; x++) {
                float4 t4 = *(const float4*)&Ks[(tr + x) * 68 + j];
                a[x][0] = t4.x; a[x][1] = t4.y; a[x][2] = t4.z; a[x][3] = t4.w;
            }
#pragma unroll
            for (int y = 0; y < 4; y++) {
                float4 t4 = *(const float4*)&Ks[(tc + y) * 68 + j];
                b[y][0] = t4.x; b[y][1] = t4.y; b[y][2] = t4.z; b[y][3] = t4.w;
            }
#pragma unroll
            for (int x = 0; x < 4; x++)
#pragma unroll
                for (int y = 0; y < 4; y++)
#pragma unroll
                    for (int m = 0; m < 4; m++)
                        acc[x][y] = fmaf(a[x][m], b[y][m], acc[x][y]);
        }
#pragma unroll
        for (int x = 0; x < 4; x++)
            *(float4*)&Gs[(tr + x) * 68 + tc] =
                make_float4(acc[x][0], acc[x][1], acc[x][2], acc[x][3]);
    }
    __syncthreads();

    if (tid < 64) {
        const int t = tid;
        float kd = 0.f;
        const float* krow = &Ks[t * 68];
        for (int d = 0; d < 64; d++) kd = fmaf(acc0s[d], krow[d], kd);
        const float* grow = &Gs[t * 68];
        for (int s = 0; s < t; s++) kd += grow[s];
        if (c == 0 && t == 0) kd = 1.f;
        invs[t] = 1.f / (kd + EPSF);
        const size_t gi = (size_t)bh * SLEN + c * 64 + t;
        const float braw = g_beta[gi];
        bprs[t] = braw * kd;
        g_beta[gi] = braw * kd;
        g_kd[gi] = kd;
    }
    __syncthreads();

    {   // write k~ in place
        const float inv = invs[r];
        float* ko = g_k + ((size_t)bid * 64 + r) * 64 + q * 16;
#pragma unroll
        for (int i = 0; i < 16; i += 4) {
            float4 x = *(const float4*)&Ks[r * 68 + q * 16 + i];
            x.x *= inv; x.y *= inv; x.z *= inv; x.w *= inv;
            *(float4*)(ko + i) = x;
        }
    }

    // forward substitution: Gs rows become M rows
    if (tid < 64) Gs[tid] = (tid == 0) ? 1.f : 0.f;
    __syncthreads();
    for (int t = 1; t < 64; t++) {
        if (tid < 64)
            tmp[tid] = (tid < t) ? bprs[t] * invs[t] * Gs[t * 68 + tid] * invs[tid]
                                 : 0.f;
        __syncthreads();
        if (tid < 64) {
            const int j = tid;
            float val = (j == t) ? 1.f : 0.f;
            for (int s = 0; s < t; s++) val = fmaf(-tmp[s], Gs[s * 68 + j], val);
            Gs[t * 68 + j] = val;
        }
        __syncthreads();
    }

    {   // write M
        float* mo = g_M + (size_t)bid * 4096 + r * 64 + q * 16;
#pragma unroll
        for (int i = 0; i < 4; i++)
            *(float4*)(mo + i * 4) = *(const float4*)&Gs[r * 68 + q * 16 + i * 4];
    }
}

// ---------------- per-chunk Q-side precompute ----------------------------------
__global__ __launch_bounds__(256) void k_prep_q() {
    const int bid = blockIdx.x;
    const int bh = bid >> 5, c = bid & 31;
    __shared__ float Qs[64 * 68];
    __shared__ float Ks[64 * 68];
    __shared__ float acc0s[64], kdws[64];
    __shared__ float denp[64][17];
    const int tid = threadIdx.x;
    const int r = tid >> 2, q = tid & 3;

    {
        const float* qg = g_q + ((size_t)bid * 64 + r) * 64 + q * 16;
        const float* kg = g_k + ((size_t)bid * 64 + r) * 64 + q * 16;
#pragma unroll
        for (int i = 0; i < 4; i++) {
            *(float4*)&Qs[r * 68 + q * 16 + i * 4] = *(const float4*)(qg + i * 4);
            *(float4*)&Ks[r * 68 + q * 16 + i * 4] = *(const float4*)(kg + i * 4);
        }
    }
    if (tid < 64) {
        acc0s[tid] = g_acc0[(size_t)bid * 64 + tid];
        kdws[tid] = g_kd[(size_t)bh * SLEN + c * 64 + tid] + EPSF;
    }
    __syncthreads();

    const int tr = (tid >> 4) << 2, tc = (tid & 15) << 2;
    float p[4][4];
#pragma unroll
    for (int x = 0; x < 4; x++)
#pragma unroll
        for (int y = 0; y < 4; y++) p[x][y] = 0.f;
    for (int j = 0; j < 64; j += 4) {
        float a[4][4], b[4][4];
#pragma unroll
        for (int x = 0; x < 4; x++) {
            float4 t4 = *(const float4*)&Qs[(tr + x) * 68 + j];
            a[x][0] = t4.x; a[x][1] = t4.y; a[x][2] = t4.z; a[x][3] = t4.w;
        }
#pragma unroll
        for (int y = 0; y < 4; y++) {
            float4 t4 = *(const float4*)&Ks[(tc + y) * 68 + j];
            b[y][0] = t4.x; b[y][1] = t4.y; b[y][2] = t4.z; b[y][3] = t4.w;
        }
#pragma unroll
        for (int x = 0; x < 4; x++)
#pragma unroll
            for (int y = 0; y < 4; y++)
#pragma unroll
                for (int m = 0; m < 4; m++)
                    p[x][y] = fmaf(a[x][m], b[y][m], p[x][y]);
    }
#pragma unroll
    for (int x = 0; x < 4; x++) {
        const int t = tr + x;
        float4 sv;
        sv.x = (tc + 0 <= t) ? p[x][0] : 0.f;
        sv.y = (tc + 1 <= t) ? p[x][1] : 0.f;
        sv.z = (tc + 2 <= t) ? p[x][2] : 0.f;
        sv.w = (tc + 3 <= t) ? p[x][3] : 0.f;
        *(float4*)(g_S + (size_t)bid * 4096 + t * 64 + tc) = sv;
        denp[t][tid & 15] = sv.x * kdws[tc + 0] + sv.y * kdws[tc + 1] +
                            sv.z * kdws[tc + 2] + sv.w * kdws[tc + 3];
    }
    __syncthreads();
    if (tid < 64) {
        const int t = tid;
        float den = 0.f;
#pragma unroll
        for (int g = 0; g < 16; g++) den += denp[t][g];
        const float* qrow = &Qs[t * 68];
        for (int d = 0; d < 64; d++) den = fmaf(acc0s[d], qrow[d], den);
        g_dinv[(size_t)bh * SLEN + c * 64 + t] = SCALEF / (den + EPSF);
    }
}

// ---------------- sequential chunk recurrence ----------------------------------
__global__ __launch_bounds__(256) void k_recur_chunk() {
    extern __shared__ float sm[];
    const int ih = blockIdx.x;
    const int bh = blockIdx.y;
    const int tid = threadIdx.x;
    float* Kc = sm;
    float* Mc = sm + 4352;
    float* Qc = sm + 8704;
    float* Sc = sm + 13056;
    float* Wt = sm + 17408;
    float* Vc = sm + 19712;
    float* Rc = sm + 22016;
    float* Uc = sm + 24320;
    float* bpr = sm + 26624;
    float* dv  = sm + 26688;

    for (int i = tid; i < 2304; i += 256) Wt[i] = 0.f;

    const int r = tid >> 2, q = tid & 3;
    const int tr = (tid >> 4) << 2;
    const int ic = (tid & 15) << 1;
    const int b_ = bh >> 4;
    const int hd = bh & 15;

    for (int c = 0; c < NCHUNK; c++) {
        __syncthreads();
        {
            const size_t row = ((size_t)bh * NCHUNK + c) * 64 + r;
            const float* kg = g_k + row * 64 + q * 16;
            const float* qg = g_q + row * 64 + q * 16;
            const size_t ms = ((size_t)bh * NCHUNK + c) * 4096 + r * 64 + q * 16;
#pragma unroll
            for (int i = 0; i < 4; i++) {
                *(float4*)&Kc[r * 68 + q * 16 + i * 4] = *(const float4*)(kg + i * 4);
                *(float4*)&Qc[r * 68 + q * 16 + i * 4] = *(const float4*)(qg + i * 4);
                *(float4*)&Mc[r * 68 + q * 16 + i * 4] = *(const float4*)(g_M + ms + i * 4);
                *(float4*)&Sc[r * 68 + q * 16 + i * 4] = *(const float4*)(g_S + ms + i * 4);
            }
            const float* vg = g_v + row * 64 + ih * 32 + q * 8;
            *(float4*)&Vc[r * 36 + q * 8]     = *(const float4*)(vg);
            *(float4*)&Vc[r * 36 + q * 8 + 4] = *(const float4*)(vg + 4);
            if (tid < 64) {
                bpr[tid] = g_beta[(size_t)bh * SLEN + c * 64 + tid];
                dv[tid]  = g_dinv[(size_t)bh * SLEN + c * 64 + tid];
            }
        }
        __syncthreads();

        // G1: Rc = diag(bpr)(Vc - Kc Wt)
        {
            float acc[4][2];
#pragma unroll
            for (int x = 0; x < 4; x++) { acc[x][0] = 0.f; acc[x][1] = 0.f; }
            for (int j = 0; j < 64; j += 4) {
                float a[4][4], wv[4][2];
#pragma unroll
                for (int x = 0; x < 4; x++) {
                    float4 t4 = *(const float4*)&Kc[(tr + x) * 68 + j];
                    a[x][0] = t4.x; a[x][1] = t4.y; a[x][2] = t4.z; a[x][3] = t4.w;
                }
#pragma unroll
                for (int m = 0; m < 4; m++) {
                    float2 t2 = *(const float2*)&Wt[(j + m) * 36 + ic];
                    wv[m][0] = t2.x; wv[m][1] = t2.y;
                }
#pragma unroll
                for (int x = 0; x < 4; x++)
#pragma unroll
                    for (int m = 0; m < 4; m++) {
                        acc[x][0] = fmaf(a[x][m], wv[m][0], acc[x][0]);
                        acc[x][1] = fmaf(a[x][m], wv[m][1], acc[x][1]);
                    }
            }
#pragma unroll
            for (int x = 0; x < 4; x++) {
                const int t = tr + x;
                const float bb = bpr[t];
                float2 vv = *(const float2*)&Vc[t * 36 + ic];
                *(float2*)&Rc[t * 36 + ic] =
                    make_float2(bb * (vv.x - acc[x][0]), bb * (vv.y - acc[x][1]));
            }
        }
        __syncthreads();

        // G2: Uc = Mc Rc
        {
            float acc[4][2];
#pragma unroll
            for (int x = 0; x < 4; x++) { acc[x][0] = 0.f; acc[x][1] = 0.f; }
            for (int s = 0; s < 64; s += 4) {
                float a[4][4], bm[4][2];
#pragma unroll
                for (int x = 0; x < 4; x++) {
                    float4 t4 = *(const float4*)&Mc[(tr + x) * 68 + s];
                    a[x][0] = t4.x; a[x][1] = t4.y; a[x][2] = t4.z; a[x][3] = t4.w;
                }
#pragma unroll
                for (int m = 0; m < 4; m++) {
                    float2 t2 = *(const float2*)&Rc[(s + m) * 36 + ic];
                    bm[m][0] = t2.x; bm[m][1] = t2.y;
                }
#pragma unroll
                for (int x = 0; x < 4; x++)
#pragma unroll
                    for (int m = 0; m < 4; m++) {
                        acc[x][0] = fmaf(a[x][m], bm[m][0], acc[x][0]);
                        acc[x][1] = fmaf(a[x][m], bm[m][1], acc[x][1]);
                    }
            }
#pragma unroll
            for (int x = 0; x < 4; x++)
                *(float2*)&Uc[(tr + x) * 36 + ic] =
                    make_float2(acc[x][0], acc[x][1]);
        }
        __syncthreads();

        // G3: Out = (Qc Wt + Sc Uc) * dv
        {
            float acc[4][2];
#pragma unroll
            for (int x = 0; x < 4; x++) { acc[x][0] = 0.f; acc[x][1] = 0.f; }
            for (int j = 0; j < 64; j += 4) {
                float a[4][4], wv[4][2];
#pragma unroll
                for (int x = 0; x < 4; x++) {
                    float4 t4 = *(const float4*)&Qc[(tr + x) * 68 + j];
                    a[x][0] = t4.x; a[x][1] = t4.y; a[x][2] = t4.z; a[x][3] = t4.w;
                }
#pragma unroll
                for (int m = 0; m < 4; m++) {
                    float2 t2 = *(const float2*)&Wt[(j + m) * 36 + ic];
                    wv[m][0] = t2.x; wv[m][1] = t2.y;
                }
#pragma unroll
                for (int x = 0; x < 4; x++)
#pragma unroll
                    for (int m = 0; m < 4; m++) {
                        acc[x][0] = fmaf(a[x][m], wv[m][0], acc[x][0]);
                        acc[x][1] = fmaf(a[x][m], wv[m][1], acc[x][1]);
                    }
            }
            for (int s = 0; s < 64; s += 4) {
                float a[4][4], bm[4][2];
#pragma unroll
                for (int x = 0; x < 4; x++) {
                    float4 t4 = *(const float4*)&Sc[(tr + x) * 68 + s];
                    a[x][0] = t4.x; a[x][1] = t4.y; a[x][2] = t4.z; a[x][3] = t4.w;
                }
#pragma unroll
                for (int m = 0; m < 4; m++) {
                    float2 t2 = *(const float2*)&Uc[(s + m) * 36 + ic];
                    bm[m][0] = t2.x; bm[m][1] = t2.y;
                }
#pragma unroll
                for (int x = 0; x < 4; x++)
#pragma unroll
                    for (int m = 0; m < 4; m++) {
                        acc[x][0] = fmaf(a[x][m], bm[m][0], acc[x][0]);
                        acc[x][1] = fmaf(a[x][m], bm[m][1], acc[x][1]);
                    }
            }
#pragma unroll
            for (int x = 0; x < 4; x++) {
                const int t = tr + x;
                const float sc = dv[t];
                const size_t o = ((size_t)(c * 64 + t) * BSZ + b_) * DM +
                                 hd * 64 + ih * 32 + ic;
                *(float2*)&g_lo[o] = make_float2(acc[x][0] * sc, acc[x][1] * sc);
            }
        }
        __syncthreads();

        // G4: Wt += Uc^T-accumulated rank-64 update
        {
            float acc[4][2];
#pragma unroll
            for (int x = 0; x < 4; x++) { acc[x][0] = 0.f; acc[x][1] = 0.f; }
#pragma unroll 8
            for (int t = 0; t < 64; t++) {
                float4 kv = *(const float4*)&Kc[t * 68 + tr];
                float2 uv = *(const float2*)&Uc[t * 36 + ic];
                acc[0][0] = fmaf(kv.x, uv.x, acc[0][0]);
                acc[0][1] = fmaf(kv.x, uv.y, acc[0][1]);
                acc[1][0] = fmaf(kv.y, uv.x, acc[1][0]);
                acc[1][1] = fmaf(kv.y, uv.y, acc[1][1]);
                acc[2][0] = fmaf(kv.z, uv.x, acc[2][0]);
                acc[2][1] = fmaf(kv.z, uv.y, acc[2][1]);
                acc[3][0] = fmaf(kv.w, uv.x, acc[3][0]);
                acc[3][1] = fmaf(kv.w, uv.y, acc[3][1]);
            }
#pragma unroll
            for (int x = 0; x < 4; x++) {
                float2 wv = *(const float2*)&Wt[(tr + x) * 36 + ic];
                wv.x += acc[x][0];
                wv.y += acc[x][1];
                *(float2*)&Wt[(tr + x) * 36 + ic] = wv;
            }
        }
    }
}

// ---------------- residual + LayerNorm, 1 block per row -----------------------
__global__ __launch_bounds__(256) void k_ln(const float* __restrict__ hin,
                                            const float* __restrict__ gamma,
                                            const float* __restrict__ beta,
                                            float* __restrict__ out) {
    int m = blockIdx.x;
    int tid = threadIdx.x;
    const float* ar = g_qkvb + (size_t)m * DM;
    const float* hr = hin + (size_t)m * DM;

    float x[4];
    float s = 0.f;
#pragma unroll
    for (int i = 0; i < 4; i++) {
        int c = tid + i * 256;
        x[i] = ar[c] + hr[c];
        s += x[i];
    }
    __shared__ float red[8];
    int wid = tid >> 5, lane = tid & 31;
#pragma unroll
    for (int o = 16; o > 0; o >>= 1) s += __shfl_xor_sync(0xffffffffu, s, o);
    if (lane == 0) red[wid] = s;
    __syncthreads();
    float tot = 0.f;
#pragma unroll
    for (int i = 0; i < 8; i++) tot += red[i];
    float mu = tot * (1.f / (float)DM);

    float v = 0.f;
#pragma unroll
    for (int i = 0; i < 4; i++) {
        float d = x[i] - mu;
        v += d * d;
    }
#pragma unroll
    for (int o = 16; o > 0; o >>= 1) v += __shfl_xor_sync(0xffffffffu, v, o);
    __syncthreads();
    if (lane == 0) red[wid] = v;
    __syncthreads();
    float vt = 0.f;
#pragma unroll
    for (int i = 0; i < 8; i++) vt += red[i];
    float rs = rsqrtf(vt * (1.f / (float)DM) + EPSF);

#pragma unroll
    for (int i = 0; i < 4; i++) {
        int c = tid + i * 256;
        out[(size_t)m * DM + c] = (x[i] - mu) * rs * gamma[c] + beta[c];
    }
}

// ---------------- launch ------------------------------------------------------
extern "C" void kernel_launch(void* const* d_in, const int* in_sizes, int n_in,
                              void* d_out, int out_size) {
    const float* h      = (const float*)d_in[0];
    const float* w_qkvb = (const float*)d_in[1];
    const float* w_o    = (const float*)d_in[2];
    const float* ln_g   = (const float*)d_in[3];
    const float* ln_b   = (const float*)d_in[4];
    float* out = (float*)d_out;

    const int k5_smem = 26752 * 4;   // 107008 bytes
    cudaFuncSetAttribute(k_recur_chunk,
                         cudaFuncAttributeMaxDynamicSharedMemorySize, 110592);

    // resolve device-global scratch addresses for the bf16-split pipeline
    unsigned *Ah, *Al, *Bh, *Bl;
    float *qkvb_f, *lo_f;
    cudaGetSymbolAddress((void**)&Ah, g_Ah);
    cudaGetSymbolAddress((void**)&Al, g_Al);
    cudaGetSymbolAddress((void**)&Bh, g_Bh);
    cudaGetSymbolAddress((void**)&Bl, g_Bl);
    cudaGetSymbolAddress((void**)&qkvb_f, g_qkvb);
    cudaGetSymbolAddress((void**)&lo_f, g_lo);

    // GEMM1: split h and w_qkvb, then tensor GEMM (M=8192, N=3088, K=1024)
    k_split16<<<M_ROWS, 256>>>(h, Ah, Al);
    k_split16<<<NQKVB, 256>>>(w_qkvb, Bh, Bl);
    k_gemm_tc<<<dim3((NQKVB + 63) / 64, M_ROWS / 128), 256>>>(Ah, Al, Bh, Bl,
                                                              qkvb_f, NQKVB);
    // activations
    k_split<<<(M_ROWS * NH) / 8, 256>>>();
    // chunked delta rule
    k_csum<<<64 * NCHUNK, 64>>>();
    k_scan<<<64, 64>>>();
    k_prep_k<<<64 * NCHUNK, 256>>>();
    k_prep_q<<<64 * NCHUNK, 256>>>();
    k_recur_chunk<<<dim3(2, 64), 256, k5_smem>>>();
    // GEMM2: split g_lo and w_o, tensor GEMM (M=8192, N=1024, K=1024)
    k_split16<<<M_ROWS, 256>>>(lo_f, Ah, Al);
    k_split16<<<DM, 256>>>(w_o, Bh, Bl);
    k_gemm_tc<<<dim3(DM / 64, M_ROWS / 128), 256>>>(Ah, Al, Bh, Bl,
                                                    qkvb_f, DM);
    // residual + layernorm
    k_ln<<<M_ROWS, 256>>>(h, ln_g, ln_b, out);
}